// round 3
// baseline (speedup 1.0000x reference)
#include <cuda_runtime.h>
#include <cooperative_groups.h>

namespace cg = cooperative_groups;

#define EPS 1e-8f
typedef unsigned long long ull;

// Shapes: b=4, m=8, n=128, d=64
__device__ float g_hgw[4 * 8 * 64];     // hg * |w|
__device__ float g_hfw[4 * 128 * 64];   // (hf + b1) * |w|
__device__ float g_htw[4 * 128 * 64];   // ht * |w|
__device__ float g_linG[4 * 8];         // sum_e hg*w
__device__ float g_linF[4 * 128];       // sum_e (hf+b1)*w
__device__ float g_linT[4 * 128];       // sum_e ht*w
__device__ unsigned g_sgnu[64];         // sign mask of W2 per e
__device__ float g_buf[4 * 8 * 128 * 128];
__device__ float g_rowpart[4 * 8 * 128];

__device__ __forceinline__ float warpReduceSum(float v) {
#pragma unroll
    for (int o = 16; o; o >>= 1) v += __shfl_xor_sync(0xffffffffu, v, o);
    return v;
}
__device__ __forceinline__ float warpReduceMax(float v) {
#pragma unroll
    for (int o = 16; o; o >>= 1) v = fmaxf(v, __shfl_xor_sync(0xffffffffu, v, o));
    return v;
}

// Packed 2-MAC of the nonlinear term: acc2 += sign2 .* |gw2 + th2|
__device__ __forceinline__ void mac2(ull& acc, ull gw, ull th, unsigned sl, unsigned sh2) {
    asm("{\n\t"
        ".reg .b64 h2, t2;\n\t"
        ".reg .b32 lo, hi;\n\t"
        "add.rn.f32x2 h2, %1, %2;\n\t"
        "mov.b64 {lo, hi}, h2;\n\t"
        "lop3.b32 lo, lo, 0x7fffffff, %3, 0x6A;\n\t"
        "lop3.b32 hi, hi, 0x7fffffff, %4, 0x6A;\n\t"
        "mov.b64 t2, {lo, hi};\n\t"
        "add.rn.f32x2 %0, %0, t2;\n\t"
        "}"
        : "+l"(acc)
        : "l"(gw), "l"(th), "r"(sl), "r"(sh2));
}

// ---------------------------------------------------------------------------
// K1 k_proj: grid (33,4) x 256 threads. Block = 8 rows x 32 e-pairs.
// Rows 0..7 = hg(m), 8..135 = hf(f) (+b1), 136..263 = ht(t). No block straddles
// a segment boundary (8 | 128 | 128, blocks of 8).
// ---------------------------------------------------------------------------
__global__ void __launch_bounds__(256) k_proj(const float* __restrict__ cities,
                                              const float* __restrict__ groups,
                                              const float* __restrict__ W1,
                                              const float* __restrict__ b1,
                                              const float* __restrict__ W2) {
    int b = blockIdx.y;
    int blk = blockIdx.x;
    int tid = threadIdx.x;
    int rloc = tid >> 5;
    int e2 = tid & 31;
    int e = 2 * e2;
    int r = blk * 8 + rloc;

    __shared__ float s_x[8][64];

    // stage the 8 input rows (coalesced)
    for (int i = tid; i < 512; i += 256) {
        int rr = i >> 6, k = i & 63;
        int rg = blk * 8 + rr;
        const float* src;
        if (rg < 8) src = groups + (b * 8 + rg) * 64;
        else if (rg < 136) src = cities + (b * 128 + (rg - 8)) * 64;
        else src = cities + (b * 128 + (rg - 136)) * 64;
        s_x[rr][k] = src[k];
    }
    if (blk == 0 && b == 0 && tid < 64) {
        g_sgnu[tid] = (W2[tid] < 0.f) ? 0x80000000u : 0u;
    }
    __syncthreads();

    float* outw;
    float* lin;
    int woff;
    bool isF = false;
    if (r < 8) {
        outw = g_hgw + (b * 8 + r) * 64;
        lin = g_linG + b * 8 + r;
        woff = 0;
    } else if (r < 136) {
        outw = g_hfw + (b * 128 + (r - 8)) * 64;
        lin = g_linF + b * 128 + (r - 8);
        woff = 64;
        isF = true;
    } else {
        outw = g_htw + (b * 128 + (r - 136)) * 64;
        lin = g_linT + b * 128 + (r - 136);
        woff = 128;
    }

    float a0 = 0.f, a1 = 0.f;
    const float2* Wp = (const float2*)(W1 + woff * 64) + e2;
#pragma unroll
    for (int k = 0; k < 64; k++) {
        float xk = s_x[rloc][k];
        float2 w = Wp[k * 32];
        a0 += xk * w.x;
        a1 += xk * w.y;
    }
    if (isF) {
        a0 += b1[e];
        a1 += b1[e + 1];
    }
    float w0 = W2[e], w1 = W2[e + 1];
    float2 st = make_float2(a0 * fabsf(w0), a1 * fabsf(w1));
    ((float2*)outw)[e2] = st;

    float p = warpReduceSum(a0 * w0 + a1 * w1);
    if (e2 == 0) *lin = p;
}

// ---------------------------------------------------------------------------
// K2 k_out: grid (128,4) x 128. Scores via 0.5*lin + 0.5*sum(sgn*| |w|h |),
// max-subtract + exp, fused with layer-0 row sums (g_rowpart).
// ---------------------------------------------------------------------------
__global__ void __launch_bounds__(128) k_out(const float* __restrict__ b2) {
    int b = blockIdx.y, f = blockIdx.x, t = threadIdx.x;
    int w = t >> 5, lane = t & 31;
    __shared__ ull sh_gw[8 * 32];
    __shared__ unsigned sh_sgu[64];
    __shared__ float sh_linG[8];
    __shared__ float s_red[8][4];
    __shared__ float s_bc[8];
    __shared__ float s_m4[4];

    for (int idx = t; idx < 256; idx += 128) {
        int m = idx >> 5, ee2 = idx & 31;
        int e = 2 * ee2;
        float a0 = g_hgw[(b * 8 + m) * 64 + e] + g_hfw[(b * 128 + f) * 64 + e];
        float a1 = g_hgw[(b * 8 + m) * 64 + e + 1] + g_hfw[(b * 128 + f) * 64 + e + 1];
        sh_gw[m * 32 + ee2] = (ull)__float_as_uint(a0) | ((ull)__float_as_uint(a1) << 32);
    }
    if (t < 64) sh_sgu[t] = g_sgnu[t];
    if (t < 8) sh_linG[t] = g_linG[b * 8 + t];
    __syncthreads();

    union {
        float4 f4[16];
        ull u[32];
    } tw;
    const float4* src = (const float4*)(g_htw + (b * 128 + t) * 64);
#pragma unroll
    for (int i = 0; i < 16; i++) tw.f4[i] = src[i];

    ull accs[8];
#pragma unroll
    for (int m = 0; m < 8; m++) accs[m] = 0ull;
#pragma unroll
    for (int ee2 = 0; ee2 < 32; ee2++) {
        unsigned sl = sh_sgu[2 * ee2], sh2 = sh_sgu[2 * ee2 + 1];
        ull th = tw.u[ee2];
#pragma unroll
        for (int m = 0; m < 8; m++) mac2(accs[m], sh_gw[m * 32 + ee2], th, sl, sh2);
    }

    float linFT = g_linF[b * 128 + f] + g_linT[b * 128 + t];
    float b2v = b2[0];
    float vals[8];
#pragma unroll
    for (int m = 0; m < 8; m++) {
        float nl = __uint_as_float((unsigned)(accs[m] & 0xffffffffull)) +
                   __uint_as_float((unsigned)(accs[m] >> 32));
        vals[m] = 0.5f * (sh_linG[m] + linFT + nl) + b2v;
    }

    if (f == 0) {
        // per-m max over t
#pragma unroll
        for (int m = 0; m < 8; m++) {
            float mm = warpReduceMax(vals[m]);
            if (lane == 0) s_red[m][w] = mm;
        }
        __syncthreads();
        if (t < 8) s_bc[t] = fmaxf(fmaxf(s_red[t][0], s_red[t][1]), fmaxf(s_red[t][2], s_red[t][3]));
        __syncthreads();
#pragma unroll
        for (int m = 0; m < 8; m++) {
            float ev = expf(vals[m] - s_bc[m]);
            g_buf[((b * 8 + m) * 128 + 0) * 128 + t] = ev;
            float s = warpReduceSum(fmaxf(ev, EPS));
            if (lane == 0) s_red[m][w] = s;
        }
        __syncthreads();
        if (t < 8)
            g_rowpart[(b * 8 + t) * 128 + 0] = s_red[t][0] + s_red[t][1] + s_red[t][2] + s_red[t][3];
    } else {
        float lm = vals[0];
#pragma unroll
        for (int m = 1; m < 8; m++) lm = fmaxf(lm, vals[m]);
        lm = warpReduceMax(lm);
        if (lane == 0) s_m4[w] = lm;
        __syncthreads();
        float mx = fmaxf(fmaxf(s_m4[0], s_m4[1]), fmaxf(s_m4[2], s_m4[3]));
#pragma unroll
        for (int m = 0; m < 8; m++) {
            float ev = expf(vals[m] - mx);
            g_buf[((b * 8 + m) * 128 + f) * 128 + t] = ev;
            float s = warpReduceSum(fmaxf(ev, EPS));
            if (lane == 0) s_red[m][w] = s;
        }
        __syncthreads();
        if (t < 8)
            g_rowpart[(b * 8 + t) * 128 + f] = s_red[t][0] + s_red[t][1] + s_red[t][2] + s_red[t][3];
    }
}

// ---------------------------------------------------------------------------
// K3 k_soft: all 10 layers. Grid 32 = 4 clusters of 8. Cluster CTA = (b, 16-y
// slab), holding ALL m and ALL x locally. Thread: x = tid&127, jq = tid>>7,
// owns v[m][jj] = P[b,m,x, y = rank*16 + jq*4 + jj].
// Even layers: den per x (cross-CTA over y -> DSMEM exchange, double-buffered).
// Odd layers:  den per y (fully CTA-local). Only 4 cluster.syncs + 1 final.
// ---------------------------------------------------------------------------
__global__ void __cluster_dims__(8, 1, 1) __launch_bounds__(512) k_soft(float* __restrict__ out) {
    cg::cluster_group cl = cg::this_cluster();
    const int rk = (int)cl.block_rank();
    const int b = blockIdx.x >> 3;
    const int tid = threadIdx.x;
    const int x = tid & 127;
    const int jq = tid >> 7;
    const int w = tid >> 5;
    const int xw = w & 3;
    const int lane = tid & 31;
    const int yb = rk * 16;
    const bool x0 = (x == 0);

    __shared__ float s_xs[2][128];   // exchanged per-x sums (sum over local y, all m)
    __shared__ float s_x0[2][8];     // exchanged per-m x==0 sums
    __shared__ float s_dinv[128];    // 1/den(x) for even layers
    __shared__ float s_d0inv[8];     // 1/den(x=0,m)
    __shared__ float s_cden[16];     // 1/den(y local) for odd layers
    __shared__ float s_c0inv[8];     // 1/den(y=0,m) (rank 0 only)
    __shared__ float s_wp[4][4][4];  // [jq][xw][jj] col partials
    __shared__ float s_w0[4][8];     // [xw][m] y==0 partials (rank 0)
    __shared__ float s_rp[4][128];   // [jq][x] row partials
    __shared__ float s_rp0[4][8];    // [jq][m] x==0 row partials

    // ---- load slab ----
    float v[8][4];
#pragma unroll
    for (int m = 0; m < 8; m++) {
        const float4* p =
            (const float4*)(g_buf + ((size_t)((b * 8 + m) * 128 + x)) * 128 + yb + jq * 4);
        float4 t4 = *p;
        v[m][0] = t4.x; v[m][1] = t4.y; v[m][2] = t4.z; v[m][3] = t4.w;
    }

    // ---- layer 0 denominators from g_rowpart ----
    if (tid < 128) {
        if (tid == 0) {
            s_dinv[0] = 0.f;
        } else {
            float d = 0.f;
#pragma unroll
            for (int m = 0; m < 8; m++) d += g_rowpart[(b * 8 + m) * 128 + tid];
            s_dinv[tid] = 1.0f / d;
        }
    }
    if (tid < 8) s_d0inv[tid] = 1.0f / g_rowpart[(b * 8 + tid) * 128];
    __syncthreads();

#pragma unroll 1
    for (int half = 0; half < 5; half++) {
        // ================= EVEN layer (2*half) =================
        {
            float rinv = s_dinv[x];
#pragma unroll
            for (int m = 0; m < 8; m++) {
                float dm = x0 ? s_d0inv[m] : rinv;
#pragma unroll
                for (int jj = 0; jj < 4; jj++) v[m][jj] = fmaxf(v[m][jj], EPS) * dm;
            }
        }
        // ---- odd-layer den prep (fully local) ----
        {
            float cp[4];
#pragma unroll
            for (int jj = 0; jj < 4; jj++) {
                float s = 0.f;
#pragma unroll
                for (int m = 0; m < 8; m++) s += fmaxf(v[m][jj], EPS);
                cp[jj] = warpReduceSum(s);
            }
            if (lane == 0) {
#pragma unroll
                for (int jj = 0; jj < 4; jj++) s_wp[jq][xw][jj] = cp[jj];
            }
            if (rk == 0 && jq == 0) {
#pragma unroll
                for (int m = 0; m < 8; m++) {
                    float s = warpReduceSum(fmaxf(v[m][0], EPS));
                    if (lane == 0) s_w0[xw][m] = s;
                }
            }
            __syncthreads();
            if (tid < 16) {
                int jqq = tid >> 2, jjj = tid & 3;
                s_cden[tid] = 1.0f / (s_wp[jqq][0][jjj] + s_wp[jqq][1][jjj] +
                                      s_wp[jqq][2][jjj] + s_wp[jqq][3][jjj]);
            }
            if (rk == 0 && tid < 8)
                s_c0inv[tid] = 1.0f / (s_w0[0][tid] + s_w0[1][tid] + s_w0[2][tid] + s_w0[3][tid]);
            __syncthreads();
        }

        // ================= ODD layer (2*half+1) =================
        float rj[4];
#pragma unroll
        for (int jj = 0; jj < 4; jj++) rj[jj] = s_cden[jq * 4 + jj];
        bool y0 = (rk == 0 && jq == 0);

        if (half == 4) {
            // layer 9: scale + store to output, done.
#pragma unroll
            for (int m = 0; m < 8; m++) {
                float4 o;
                o.x = fmaxf(v[m][0], EPS) * (y0 ? s_c0inv[m] : rj[0]);
                o.y = fmaxf(v[m][1], EPS) * rj[1];
                o.z = fmaxf(v[m][2], EPS) * rj[2];
                o.w = fmaxf(v[m][3], EPS) * rj[3];
                *(float4*)(out + ((size_t)((b * 8 + m) * 128 + x)) * 128 + yb + jq * 4) = o;
            }
            break;
        }

#pragma unroll
        for (int m = 0; m < 8; m++) {
            v[m][0] = fmaxf(v[m][0], EPS) * (y0 ? s_c0inv[m] : rj[0]);
#pragma unroll
            for (int jj = 1; jj < 4; jj++) v[m][jj] = fmaxf(v[m][jj], EPS) * rj[jj];
        }

        // ---- even-layer den prep: local partials + DSMEM exchange ----
        int p = half & 1;
        {
            float rp = 0.f;
#pragma unroll
            for (int m = 0; m < 8; m++) {
#pragma unroll
                for (int jj = 0; jj < 4; jj++) rp += fmaxf(v[m][jj], EPS);
            }
            s_rp[jq][x] = rp;
            if (x0) {
#pragma unroll
                for (int m = 0; m < 8; m++) {
                    float s = fmaxf(v[m][0], EPS) + fmaxf(v[m][1], EPS) +
                              fmaxf(v[m][2], EPS) + fmaxf(v[m][3], EPS);
                    s_rp0[jq][m] = s;
                }
            }
            __syncthreads();
            if (tid < 128)
                s_xs[p][tid] = s_rp[0][tid] + s_rp[1][tid] + s_rp[2][tid] + s_rp[3][tid];
            if (tid < 8)
                s_x0[p][tid] = s_rp0[0][tid] + s_rp0[1][tid] + s_rp0[2][tid] + s_rp0[3][tid];
        }
        cl.sync();

        // ---- read peers' sums -> next even dens ----
        if (tid < 128) {
            if (tid == 0) {
                s_dinv[0] = 0.f;
            } else {
                float d = 0.f;
#pragma unroll
                for (int r = 0; r < 8; r++) {
                    const float* pp = cl.map_shared_rank((const float*)&s_xs[p][0], r);
                    d += pp[tid];
                }
                s_dinv[tid] = 1.0f / d;
            }
        }
        if (tid < 8) {
            float d = 0.f;
#pragma unroll
            for (int r = 0; r < 8; r++) {
                const float* pp = cl.map_shared_rank((const float*)&s_x0[p][0], r);
                d += pp[tid];
            }
            s_d0inv[tid] = 1.0f / d;
        }
        __syncthreads();
    }

    cl.sync();  // keep SMEM alive until all peers finished DSMEM reads
}

// ---------------------------------------------------------------------------
// Launch: 3 kernels.
// ---------------------------------------------------------------------------
extern "C" void kernel_launch(void* const* d_in, const int* in_sizes, int n_in,
                              void* d_out, int out_size) {
    const float* cities = (const float*)d_in[0];
    const float* groups = (const float*)d_in[1];
    const float* W1 = (const float*)d_in[2];
    const float* b1 = (const float*)d_in[3];
    const float* W2 = (const float*)d_in[4];
    const float* b2 = (const float*)d_in[5];
    float* out = (float*)d_out;

    k_proj<<<dim3(33, 4), 256>>>(cities, groups, W1, b1, W2);
    k_out<<<dim3(128, 4), 128>>>(b2);
    k_soft<<<32, 512>>>(out);
}